// round 10
// baseline (speedup 1.0000x reference)
#include <cuda_runtime.h>
#include <math.h>
#include <stdint.h>

#define BATCH 64
#define SEQT  2048
#define ISZ   256
#define HSZ   1024

// ---------------------------------------------------------------------------
// Global scratch (module-compact layouts).
//  XP_m[k][b][128] : input projection at module-m active times (t = k<<m)
//  HT_m[k][b][128] : module-m hidden trajectory samples
//  U_j [k][b][128j]: Whh[0:128j, j-block] @ h_j^(k)
//  C_m [k][b][256] : fc_w[:, m-block] @ h_m^(k)
// ---------------------------------------------------------------------------
#define XP_TOT 33423360ull
#define U_TOT  32374784ull
#define C_TOT  66846720ull
static __device__ float g_xp[XP_TOT];
static __device__ float g_ht[XP_TOT];
static __device__ float g_u [U_TOT];
static __device__ float g_c [C_TOT];

__host__ __device__ constexpr size_t xpoff(int m) {
    return 8192ull * (size_t)(4096 - (4096 >> m));
}
__host__ __device__ constexpr size_t uoff(int j) {
    size_t s = 0;
    for (int p = 1; p < j; p++) s += (size_t)(2048 >> p) * 8192ull * (size_t)p;
    return s;
}
__host__ __device__ constexpr size_t coff(int m) {
    return 16384ull * (size_t)(4096 - (4096 >> m));
}

// ---------------------------------------------------------------------------
// TF32 3-split GEMM core (fp32-accurate): 128x128 CTA tile, 256 thr, 8 warps,
// warp tile 32x64, mma.m16n8k8, double-buffered smem stage.
// ---------------------------------------------------------------------------
__device__ __forceinline__ uint32_t f32_to_tf32(float x) {
    uint32_t r;
    asm("cvt.rna.tf32.f32 %0, %1;" : "=r"(r) : "f"(x));
    return r;
}
__device__ __forceinline__ void mma_tf32(float4& d, const uint32_t a[4],
                                         const uint32_t b0, const uint32_t b1) {
    asm volatile(
        "mma.sync.aligned.m16n8k8.row.col.f32.tf32.tf32.f32 "
        "{%0,%1,%2,%3}, {%4,%5,%6,%7}, {%8,%9}, {%0,%1,%2,%3};"
        : "+f"(d.x), "+f"(d.y), "+f"(d.z), "+f"(d.w)
        : "r"(a[0]), "r"(a[1]), "r"(a[2]), "r"(a[3]), "r"(b0), "r"(b1));
}

#define GST 4224
#define GEMM_SMEM_BYTES (2 * GST * 4)

__device__ __forceinline__ void stage_chunk(float* s, const float4 av, const float4 bv,
                                            int ldr, int ldk)
{
    const float a4[4] = {av.x, av.y, av.z, av.w};
    const float b4[4] = {bv.x, bv.y, bv.z, bv.w};
#pragma unroll
    for (int e = 0; e < 4; e++) {
        uint32_t hi = f32_to_tf32(a4[e]);
        float lo = a4[e] - __uint_as_float(hi);
        s[(ldk + e) * 132 + ldr]        = __uint_as_float(hi);
        s[1056 + (ldk + e) * 132 + ldr] = __uint_as_float(f32_to_tf32(lo));
        uint32_t bhi = f32_to_tf32(b4[e]);
        float blo = b4[e] - __uint_as_float(bhi);
        s[2112 + (ldk + e) * 132 + ldr] = __uint_as_float(bhi);
        s[3168 + (ldk + e) * 132 + ldr] = __uint_as_float(f32_to_tf32(blo));
    }
}

__device__ __forceinline__ void gemm_core(const float* Ag, const float* Bg,
                                          int kchunks, float* gsm,
                                          int ldr, int ldk, int m0, int n0, int tig,
                                          float4 acc[2][8])
{
    stage_chunk(gsm, *(const float4*)Ag, *(const float4*)Bg, ldr, ldk);
    __syncthreads();

    for (int kc = 0; kc < kchunks; kc++) {
        float4 av, bv;
        if (kc + 1 < kchunks) {
            av = *(const float4*)(Ag + (kc + 1) * 8);
            bv = *(const float4*)(Bg + (kc + 1) * 8);
        }
        const float* As_h = gsm + (kc & 1) * GST;
        const float* As_l = As_h + 1056;
        const float* Bs_h = As_h + 2112;
        const float* Bs_l = As_h + 3168;

        uint32_t ah[2][4], al[2][4];
#pragma unroll
        for (int mt = 0; mt < 2; mt++) {
            const int r = m0 + mt * 16;
            ah[mt][0] = __float_as_uint(As_h[tig * 132 + r]);
            ah[mt][1] = __float_as_uint(As_h[tig * 132 + r + 8]);
            ah[mt][2] = __float_as_uint(As_h[(tig + 4) * 132 + r]);
            ah[mt][3] = __float_as_uint(As_h[(tig + 4) * 132 + r + 8]);
            al[mt][0] = __float_as_uint(As_l[tig * 132 + r]);
            al[mt][1] = __float_as_uint(As_l[tig * 132 + r + 8]);
            al[mt][2] = __float_as_uint(As_l[(tig + 4) * 132 + r]);
            al[mt][3] = __float_as_uint(As_l[(tig + 4) * 132 + r + 8]);
        }
#pragma unroll
        for (int nt = 0; nt < 8; nt++) {
            const int cn = n0 + nt * 8;
            uint32_t bh0 = __float_as_uint(Bs_h[tig * 132 + cn]);
            uint32_t bh1 = __float_as_uint(Bs_h[(tig + 4) * 132 + cn]);
            uint32_t bl0 = __float_as_uint(Bs_l[tig * 132 + cn]);
            uint32_t bl1 = __float_as_uint(Bs_l[(tig + 4) * 132 + cn]);
#pragma unroll
            for (int mt = 0; mt < 2; mt++) {
                mma_tf32(acc[mt][nt], al[mt], bh0, bh1);
                mma_tf32(acc[mt][nt], ah[mt], bl0, bl1);
                mma_tf32(acc[mt][nt], ah[mt], bh0, bh1);
            }
        }

        if (kc + 1 < kchunks)
            stage_chunk(gsm + ((kc + 1) & 1) * GST, av, bv, ldr, ldk);
        __syncthreads();
    }
}

// ---------------------------------------------------------------------------
// Fused XP GEMM: one launch for all 8 modules (2040 tiles).
// ---------------------------------------------------------------------------
__global__ __launch_bounds__(256, 2)
void gemm_xp(const float* __restrict__ X, const float* __restrict__ Wih)
{
    extern __shared__ float gsm[];
    const int tid = threadIdx.x;
    const int wid = tid >> 5;
    const int lane = tid & 31;
    const int grp = lane >> 2;
    const int tig = lane & 3;
    const int warpRow = wid >> 1;
    const int warpCol = wid & 1;
    const int ldr = tid >> 1;
    const int ldk = (tid & 1) << 2;

    int Y = blockIdx.x;
    int m = 0, base = 0, cnt = 1024;
    while (Y >= base + cnt && m < 7) { base += cnt; m++; cnt >>= 1; }
    const int ty = Y - base;

    const int rowg = ty * 128 + ldr;
    const int bb = rowg & 63;
    const int kk = rowg >> 6;
    const float* Ag = X + ((size_t)bb * 2048 + ((size_t)kk << m)) * 256 + ldk;
    const float* Bg = Wih + ((size_t)(128 * m + ldr)) * 256 + ldk;

    float4 acc[2][8];
#pragma unroll
    for (int i = 0; i < 2; i++)
#pragma unroll
        for (int j = 0; j < 8; j++) acc[i][j] = make_float4(0.f, 0.f, 0.f, 0.f);

    gemm_core(Ag, Bg, 32, gsm, ldr, ldk, warpRow * 32 + grp, warpCol * 64 + grp, tig, acc);

    float* C = g_xp + xpoff(m);
#pragma unroll
    for (int nt = 0; nt < 8; nt++) {
        const int col = warpCol * 64 + nt * 8 + tig * 2;
#pragma unroll
        for (int mt = 0; mt < 2; mt++) {
            const int r0 = ty * 128 + warpRow * 32 + mt * 16 + grp;
            float4 d = acc[mt][nt];
            *(float2*)(C + (size_t)r0 * 128 + col)       = make_float2(d.x, d.y);
            *(float2*)(C + (size_t)(r0 + 8) * 128 + col) = make_float2(d.z, d.w);
        }
    }
}

// ---------------------------------------------------------------------------
// U-only GEMM for module j: U_j = ht_j @ Whh[0:128j, j-block]^T
// grid = (j, 1024>>j). K = 128.
// ---------------------------------------------------------------------------
__global__ __launch_bounds__(256, 2)
void gemm_u(const float* __restrict__ A, const float* __restrict__ B1,
            float* __restrict__ C1, int ldc1)
{
    extern __shared__ float gsm[];
    const int bn = blockIdx.x;
    const int bm = blockIdx.y;
    const int tid = threadIdx.x;
    const int wid = tid >> 5;
    const int lane = tid & 31;
    const int grp = lane >> 2;
    const int tig = lane & 3;
    const int warpRow = wid >> 1;
    const int warpCol = wid & 1;
    const int ldr = tid >> 1;
    const int ldk = (tid & 1) << 2;

    const float* Ag = A + (size_t)(bm * 128 + ldr) * 128 + ldk;
    const float* Bg = B1 + (size_t)(bn * 128 + ldr) * 1024 + ldk;

    float4 acc[2][8];
#pragma unroll
    for (int i = 0; i < 2; i++)
#pragma unroll
        for (int j = 0; j < 8; j++) acc[i][j] = make_float4(0.f, 0.f, 0.f, 0.f);

    gemm_core(Ag, Bg, 16, gsm, ldr, ldk, warpRow * 32 + grp, warpCol * 64 + grp, tig, acc);

#pragma unroll
    for (int nt = 0; nt < 8; nt++) {
        const int col = bn * 128 + warpCol * 64 + nt * 8 + tig * 2;
#pragma unroll
        for (int mt = 0; mt < 2; mt++) {
            const int r0 = bm * 128 + warpRow * 32 + mt * 16 + grp;
            float4 d = acc[mt][nt];
            *(float2*)(C1 + (size_t)r0 * ldc1 + col)       = make_float2(d.x, d.y);
            *(float2*)(C1 + (size_t)(r0 + 8) * ldc1 + col) = make_float2(d.z, d.w);
        }
    }
}

// ---------------------------------------------------------------------------
// Fused C GEMM: ALL modules in one launch. grid = (2, 2040); row-tile Y decodes
// module m (1024>>m tiles each). C_m = ht_m @ fcw[:, m-block]^T, K=128, N=256.
// ---------------------------------------------------------------------------
__global__ __launch_bounds__(256, 2)
void gemm_c(const float* __restrict__ fcw)
{
    extern __shared__ float gsm[];
    const int bn = blockIdx.x;
    const int tid = threadIdx.x;
    const int wid = tid >> 5;
    const int lane = tid & 31;
    const int grp = lane >> 2;
    const int tig = lane & 3;
    const int warpRow = wid >> 1;
    const int warpCol = wid & 1;
    const int ldr = tid >> 1;
    const int ldk = (tid & 1) << 2;

    int Y = blockIdx.y;
    int m = 0, base = 0, cnt = 1024;
    while (Y >= base + cnt && m < 7) { base += cnt; m++; cnt >>= 1; }
    const int ty = Y - base;

    const float* Ag = g_ht + xpoff(m) + (size_t)(ty * 128 + ldr) * 128 + ldk;
    const float* Bg = fcw + 128 * m + (size_t)(bn * 128 + ldr) * 1024 + ldk;

    float4 acc[2][8];
#pragma unroll
    for (int i = 0; i < 2; i++)
#pragma unroll
        for (int j = 0; j < 8; j++) acc[i][j] = make_float4(0.f, 0.f, 0.f, 0.f);

    gemm_core(Ag, Bg, 16, gsm, ldr, ldk, warpRow * 32 + grp, warpCol * 64 + grp, tig, acc);

    float* C = g_c + coff(m);
#pragma unroll
    for (int nt = 0; nt < 8; nt++) {
        const int col = bn * 128 + warpCol * 64 + nt * 8 + tig * 2;
#pragma unroll
        for (int mt = 0; mt < 2; mt++) {
            const int r0 = ty * 128 + warpRow * 32 + mt * 16 + grp;
            float4 d = acc[mt][nt];
            *(float2*)(C + (size_t)r0 * 256 + col)       = make_float2(d.x, d.y);
            *(float2*)(C + (size_t)(r0 + 8) * 256 + col) = make_float2(d.z, d.w);
        }
    }
}

// ---------------------------------------------------------------------------
// Chain kernel: 128-dim sequential recurrence, latency-optimized step.
//  - 256 threads, pair-per-row (row = tid>>1, sub = tid&1, same warp)
//  - W half-row pinned in 16 float4 regs; reduce = 1 shfl_xor
//  - double-buffered h -> ONE __syncthreads per step
//  - cp.async depth-3 pipeline (ring of 4 smem slots) for xp/u inputs
//  - fast tanh: 1 - 2/(e^{2x}+1) via __expf (+clamp)
// ---------------------------------------------------------------------------
__device__ __forceinline__ uint32_t smem_u32c(const void* p) {
    uint32_t a;
    asm("{ .reg .u64 t; cvta.to.shared.u64 t, %1; cvt.u32.u64 %0, t; }" : "=r"(a) : "l"(p));
    return a;
}

template<int MM>
__global__ __launch_bounds__(256, 1)
void chain_kernel(const float* __restrict__ Whh, const float* __restrict__ bih,
                  const float* __restrict__ bhh)
{
    constexpr int KS   = 2048 >> MM;
    constexpr int NU   = 7 - MM;
    constexpr int NSTR = NU + 1;

    const int b   = blockIdx.x;
    const int tid = threadIdx.x;
    const int row = tid >> 1;
    const int sub = tid & 1;

    // pinned W half-row
    float4 w[16];
    const float4* wrow = (const float4*)(Whh + (size_t)(128 * MM + row) * 1024
                                          + 128 * MM + 64 * sub);
#pragma unroll
    for (int q = 0; q < 16; q++) w[q] = __ldg(wrow + q);

    const float bsr = __ldg(bih + 128 * MM + row) + __ldg(bhh + 128 * MM + row);

    __shared__ __align__(16) float hbuf[2][128];
    __shared__ __align__(16) float stage[4][NSTR][128];

    const float* xp = g_xp + xpoff(MM) + (size_t)b * 128;
    float* ht = g_ht + xpoff(MM) + (size_t)b * 128;

    if (tid < 128) hbuf[1][tid] = 0.f;   // h^{-1} = 0 (read at k=0)

    // cp.async stage issuer for step s (thread tid handles one 16B segment)
    auto issue_stage = [&](int s) {
        if (tid < NSTR * 32) {
            const int str = tid >> 5;
            const int seg = tid & 31;
            const float* src;
            if (str == 0) {
                src = xp + (size_t)s * 8192 + seg * 4;
            } else {
                const int e = str - 1;
                const int j = MM + 1 + e;
                const int t_idx = (s > 0) ? (((s << MM) - 1) >> j) : 0;
                src = g_u + uoff(j) + (size_t)b * (128 * j) + 128 * MM
                      + (size_t)t_idx * (size_t)(8192 * j) + seg * 4;
            }
            uint32_t dst = smem_u32c(&stage[s & 3][str][seg * 4]);
            asm volatile("cp.async.ca.shared.global [%0], [%1], 16;"
                         :: "r"(dst), "l"(src) : "memory");
        }
    };

    // preload steps 0..2 (depth 3)
    issue_stage(0);
    asm volatile("cp.async.commit_group;" ::: "memory");
    issue_stage(1);
    asm volatile("cp.async.commit_group;" ::: "memory");
    issue_stage(2);
    asm volatile("cp.async.commit_group;" ::: "memory");
    asm volatile("cp.async.wait_group 2;" ::: "memory");
    __syncthreads();

    for (int k = 0; k < KS; k++) {
        // dot: W[row, sub-half] . h^{k-1}[sub-half]
        const float4* hp = (const float4*)hbuf[(k + 1) & 1] + sub * 16;
        float a0 = 0.f, a1 = 0.f, a2 = 0.f, a3 = 0.f;
#pragma unroll
        for (int q = 0; q < 4; q++) {
            float4 h0 = hp[4 * q + 0], h1 = hp[4 * q + 1];
            float4 h2 = hp[4 * q + 2], h3 = hp[4 * q + 3];
            float4 w0 = w[4 * q + 0], w1 = w[4 * q + 1];
            float4 w2 = w[4 * q + 2], w3 = w[4 * q + 3];
            a0 = fmaf(w0.x, h0.x, fmaf(w0.y, h0.y, fmaf(w0.z, h0.z, fmaf(w0.w, h0.w, a0))));
            a1 = fmaf(w1.x, h1.x, fmaf(w1.y, h1.y, fmaf(w1.z, h1.z, fmaf(w1.w, h1.w, a1))));
            a2 = fmaf(w2.x, h2.x, fmaf(w2.y, h2.y, fmaf(w2.z, h2.z, fmaf(w2.w, h2.w, a2))));
            a3 = fmaf(w3.x, h3.x, fmaf(w3.y, h3.y, fmaf(w3.z, h3.z, fmaf(w3.w, h3.w, a3))));
        }
        float acc = (a0 + a1) + (a2 + a3);
        acc += __shfl_xor_sync(0xffffffffu, acc, 1);

        // keep the pipeline fed (depth 3); always commit for uniform accounting
        if (k + 3 < KS) issue_stage(k + 3);
        asm volatile("cp.async.commit_group;" ::: "memory");

        if (sub == 0) {
            const float* st = &stage[k & 3][0][0];
            float z = st[row] + bsr + acc;
            if (k > 0) {
#pragma unroll
                for (int e = 0; e < NU; e++) z += st[(e + 1) * 128 + row];
            }
            // fast tanh
            float xz = fminf(fmaxf(z, -15.f), 15.f);
            float ex = __expf(2.f * xz);
            float hn = 1.f - __fdividef(2.f, ex + 1.f);
            hbuf[k & 1][row] = hn;
            ht[(size_t)k * 8192 + row] = hn;
        }

        asm volatile("cp.async.wait_group 2;" ::: "memory");
        __syncthreads();
    }
}

// ---------------------------------------------------------------------------
// Gather: y[b][t][i] = fc_b[i] + sum_m C_m[(t>>m)*64 + b][i]
// ---------------------------------------------------------------------------
__global__ __launch_bounds__(256)
void gather_y(const float* __restrict__ fcb, float* __restrict__ out)
{
    const int i = threadIdx.x;
    const float bias = __ldg(fcb + i);
#pragma unroll 1
    for (int e = 0; e < 8; e++) {
        const int tb = blockIdx.x * 8 + e;
        const int t = tb >> 6;
        const int b = tb & 63;
        float v = bias;
#pragma unroll
        for (int m = 0; m < 8; m++)
            v += g_c[coff(m) + (((size_t)((t >> m) * 64 + b)) << 8) + i];
        out[((size_t)b * 2048 + t) * 256 + i] = v;
    }
}

// ---------------------------------------------------------------------------
// Launch: XP(1) -> [chain_j -> U_j]_{j=7..1} -> chain_0 -> C(all, 1) -> gather.
// 18 launches, one stream, graph-capturable, allocation-free.
// ---------------------------------------------------------------------------
extern "C" void kernel_launch(void* const* d_in, const int* in_sizes, int n_in,
                              void* d_out, int out_size)
{
    const float* x   = (const float*)d_in[0];
    const float* wih = (const float*)d_in[1];
    const float* whh = (const float*)d_in[2];
    const float* bih = (const float*)d_in[3];
    const float* bhh = (const float*)d_in[4];
    const float* fcw = (const float*)d_in[5];
    const float* fcb = (const float*)d_in[6];
    float* out = (float*)d_out;

    void* p;
    cudaGetSymbolAddress(&p, g_ht); float* pht = (float*)p;
    cudaGetSymbolAddress(&p, g_u);  float* pu  = (float*)p;

    cudaFuncSetAttribute(gemm_xp, cudaFuncAttributeMaxDynamicSharedMemorySize, GEMM_SMEM_BYTES);
    cudaFuncSetAttribute(gemm_u,  cudaFuncAttributeMaxDynamicSharedMemorySize, GEMM_SMEM_BYTES);
    cudaFuncSetAttribute(gemm_c,  cudaFuncAttributeMaxDynamicSharedMemorySize, GEMM_SMEM_BYTES);

    // all input projections in one full-chip launch (2040 tiles)
    gemm_xp<<<2040, 256, GEMM_SMEM_BYTES>>>(x, wih);

    // cascade: chain_j then U_j (critical path only; C deferred)
#define RUN_STAGE(j)                                                            \
    do {                                                                        \
        chain_kernel<j><<<BATCH, 256>>>(whh, bih, bhh);                         \
        dim3 g((unsigned)(j), (unsigned)(1024 >> (j)));                         \
        gemm_u<<<g, 256, GEMM_SMEM_BYTES>>>(                                    \
            pht + xpoff(j), whh + 128 * (j), pu + uoff(j), 128 * (j));          \
    } while (0)

    RUN_STAGE(7);
    RUN_STAGE(6);
    RUN_STAGE(5);
    RUN_STAGE(4);
    RUN_STAGE(3);
    RUN_STAGE(2);
    RUN_STAGE(1);

    chain_kernel<0><<<BATCH, 256>>>(whh, bih, bhh);

    // all fc contributions in one full-chip launch (2 x 2040 tiles)
    {
        dim3 g(2, 2040);
        gemm_c<<<g, 256, GEMM_SMEM_BYTES>>>(fcw);
    }

    gather_y<<<16384, 256>>>(fcb, out);
#undef RUN_STAGE
}

// round 11
// speedup vs baseline: 1.2254x; 1.2254x over previous
#include <cuda_runtime.h>
#include <math.h>
#include <stdint.h>

#define BATCH 64
#define SEQT  2048
#define ISZ   256
#define HSZ   1024

// ---------------------------------------------------------------------------
// Global scratch (module-compact layouts).
//  XP_m[k][b][128] : input projection at module-m active times (t = k<<m)
//  HT_m[k][b][128] : module-m hidden trajectory samples
//  U_j [k][b][128j]: Whh[0:128j, j-block] @ h_j^(k)
//  C_m [k][b][256] : fc_w[:, m-block] @ h_m^(k)
// ---------------------------------------------------------------------------
#define XP_TOT 33423360ull
#define U_TOT  32374784ull
#define C_TOT  66846720ull
static __device__ float g_xp[XP_TOT];
static __device__ float g_ht[XP_TOT];
static __device__ float g_u [U_TOT];
static __device__ float g_c [C_TOT];

__host__ __device__ constexpr size_t xpoff(int m) {
    return 8192ull * (size_t)(4096 - (4096 >> m));
}
__host__ __device__ constexpr size_t uoff(int j) {
    size_t s = 0;
    for (int p = 1; p < j; p++) s += (size_t)(2048 >> p) * 8192ull * (size_t)p;
    return s;
}
__host__ __device__ constexpr size_t coff(int m) {
    return 16384ull * (size_t)(4096 - (4096 >> m));
}

// ---------------------------------------------------------------------------
// TF32 3-split GEMM core (fp32-accurate): 128x128 CTA tile, 256 thr, 8 warps,
// warp tile 32x64, mma.m16n8k8, double-buffered smem stage.
// ---------------------------------------------------------------------------
__device__ __forceinline__ uint32_t f32_to_tf32(float x) {
    uint32_t r;
    asm("cvt.rna.tf32.f32 %0, %1;" : "=r"(r) : "f"(x));
    return r;
}
__device__ __forceinline__ void mma_tf32(float4& d, const uint32_t a[4],
                                         const uint32_t b0, const uint32_t b1) {
    asm volatile(
        "mma.sync.aligned.m16n8k8.row.col.f32.tf32.tf32.f32 "
        "{%0,%1,%2,%3}, {%4,%5,%6,%7}, {%8,%9}, {%0,%1,%2,%3};"
        : "+f"(d.x), "+f"(d.y), "+f"(d.z), "+f"(d.w)
        : "r"(a[0]), "r"(a[1]), "r"(a[2]), "r"(a[3]), "r"(b0), "r"(b1));
}

#define GST 4224
#define GEMM_SMEM_BYTES (2 * GST * 4)

__device__ __forceinline__ void stage_chunk(float* s, const float4 av, const float4 bv,
                                            int ldr, int ldk)
{
    const float a4[4] = {av.x, av.y, av.z, av.w};
    const float b4[4] = {bv.x, bv.y, bv.z, bv.w};
#pragma unroll
    for (int e = 0; e < 4; e++) {
        uint32_t hi = f32_to_tf32(a4[e]);
        float lo = a4[e] - __uint_as_float(hi);
        s[(ldk + e) * 132 + ldr]        = __uint_as_float(hi);
        s[1056 + (ldk + e) * 132 + ldr] = __uint_as_float(f32_to_tf32(lo));
        uint32_t bhi = f32_to_tf32(b4[e]);
        float blo = b4[e] - __uint_as_float(bhi);
        s[2112 + (ldk + e) * 132 + ldr] = __uint_as_float(bhi);
        s[3168 + (ldk + e) * 132 + ldr] = __uint_as_float(f32_to_tf32(blo));
    }
}

__device__ __forceinline__ void gemm_core(const float* Ag, const float* Bg,
                                          int kchunks, float* gsm,
                                          int ldr, int ldk, int m0, int n0, int tig,
                                          float4 acc[2][8])
{
    stage_chunk(gsm, *(const float4*)Ag, *(const float4*)Bg, ldr, ldk);
    __syncthreads();

    for (int kc = 0; kc < kchunks; kc++) {
        float4 av, bv;
        if (kc + 1 < kchunks) {
            av = *(const float4*)(Ag + (kc + 1) * 8);
            bv = *(const float4*)(Bg + (kc + 1) * 8);
        }
        const float* As_h = gsm + (kc & 1) * GST;
        const float* As_l = As_h + 1056;
        const float* Bs_h = As_h + 2112;
        const float* Bs_l = As_h + 3168;

        uint32_t ah[2][4], al[2][4];
#pragma unroll
        for (int mt = 0; mt < 2; mt++) {
            const int r = m0 + mt * 16;
            ah[mt][0] = __float_as_uint(As_h[tig * 132 + r]);
            ah[mt][1] = __float_as_uint(As_h[tig * 132 + r + 8]);
            ah[mt][2] = __float_as_uint(As_h[(tig + 4) * 132 + r]);
            ah[mt][3] = __float_as_uint(As_h[(tig + 4) * 132 + r + 8]);
            al[mt][0] = __float_as_uint(As_l[tig * 132 + r]);
            al[mt][1] = __float_as_uint(As_l[tig * 132 + r + 8]);
            al[mt][2] = __float_as_uint(As_l[(tig + 4) * 132 + r]);
            al[mt][3] = __float_as_uint(As_l[(tig + 4) * 132 + r + 8]);
        }
#pragma unroll
        for (int nt = 0; nt < 8; nt++) {
            const int cn = n0 + nt * 8;
            uint32_t bh0 = __float_as_uint(Bs_h[tig * 132 + cn]);
            uint32_t bh1 = __float_as_uint(Bs_h[(tig + 4) * 132 + cn]);
            uint32_t bl0 = __float_as_uint(Bs_l[tig * 132 + cn]);
            uint32_t bl1 = __float_as_uint(Bs_l[(tig + 4) * 132 + cn]);
#pragma unroll
            for (int mt = 0; mt < 2; mt++) {
                mma_tf32(acc[mt][nt], al[mt], bh0, bh1);
                mma_tf32(acc[mt][nt], ah[mt], bl0, bl1);
                mma_tf32(acc[mt][nt], ah[mt], bh0, bh1);
            }
        }

        if (kc + 1 < kchunks)
            stage_chunk(gsm + ((kc + 1) & 1) * GST, av, bv, ldr, ldk);
        __syncthreads();
    }
}

// ---------------------------------------------------------------------------
// Fused XP GEMM: one launch for all 8 modules (2040 tiles).
// ---------------------------------------------------------------------------
__global__ __launch_bounds__(256, 2)
void gemm_xp(const float* __restrict__ X, const float* __restrict__ Wih)
{
    extern __shared__ float gsm[];
    const int tid = threadIdx.x;
    const int wid = tid >> 5;
    const int lane = tid & 31;
    const int grp = lane >> 2;
    const int tig = lane & 3;
    const int warpRow = wid >> 1;
    const int warpCol = wid & 1;
    const int ldr = tid >> 1;
    const int ldk = (tid & 1) << 2;

    int Y = blockIdx.x;
    int m = 0, base = 0, cnt = 1024;
    while (Y >= base + cnt && m < 7) { base += cnt; m++; cnt >>= 1; }
    const int ty = Y - base;

    const int rowg = ty * 128 + ldr;
    const int bb = rowg & 63;
    const int kk = rowg >> 6;
    const float* Ag = X + ((size_t)bb * 2048 + ((size_t)kk << m)) * 256 + ldk;
    const float* Bg = Wih + ((size_t)(128 * m + ldr)) * 256 + ldk;

    float4 acc[2][8];
#pragma unroll
    for (int i = 0; i < 2; i++)
#pragma unroll
        for (int j = 0; j < 8; j++) acc[i][j] = make_float4(0.f, 0.f, 0.f, 0.f);

    gemm_core(Ag, Bg, 32, gsm, ldr, ldk, warpRow * 32 + grp, warpCol * 64 + grp, tig, acc);

    float* C = g_xp + xpoff(m);
#pragma unroll
    for (int nt = 0; nt < 8; nt++) {
        const int col = warpCol * 64 + nt * 8 + tig * 2;
#pragma unroll
        for (int mt = 0; mt < 2; mt++) {
            const int r0 = ty * 128 + warpRow * 32 + mt * 16 + grp;
            float4 d = acc[mt][nt];
            *(float2*)(C + (size_t)r0 * 128 + col)       = make_float2(d.x, d.y);
            *(float2*)(C + (size_t)(r0 + 8) * 128 + col) = make_float2(d.z, d.w);
        }
    }
}

// ---------------------------------------------------------------------------
// U-only GEMM for module j: U_j = ht_j @ Whh[0:128j, j-block]^T
// grid = (j, 1024>>j). K = 128.
// ---------------------------------------------------------------------------
__global__ __launch_bounds__(256, 2)
void gemm_u(const float* __restrict__ A, const float* __restrict__ B1,
            float* __restrict__ C1, int ldc1)
{
    extern __shared__ float gsm[];
    const int bn = blockIdx.x;
    const int bm = blockIdx.y;
    const int tid = threadIdx.x;
    const int wid = tid >> 5;
    const int lane = tid & 31;
    const int grp = lane >> 2;
    const int tig = lane & 3;
    const int warpRow = wid >> 1;
    const int warpCol = wid & 1;
    const int ldr = tid >> 1;
    const int ldk = (tid & 1) << 2;

    const float* Ag = A + (size_t)(bm * 128 + ldr) * 128 + ldk;
    const float* Bg = B1 + (size_t)(bn * 128 + ldr) * 1024 + ldk;

    float4 acc[2][8];
#pragma unroll
    for (int i = 0; i < 2; i++)
#pragma unroll
        for (int j = 0; j < 8; j++) acc[i][j] = make_float4(0.f, 0.f, 0.f, 0.f);

    gemm_core(Ag, Bg, 16, gsm, ldr, ldk, warpRow * 32 + grp, warpCol * 64 + grp, tig, acc);

#pragma unroll
    for (int nt = 0; nt < 8; nt++) {
        const int col = bn * 128 + warpCol * 64 + nt * 8 + tig * 2;
#pragma unroll
        for (int mt = 0; mt < 2; mt++) {
            const int r0 = bm * 128 + warpRow * 32 + mt * 16 + grp;
            float4 d = acc[mt][nt];
            *(float2*)(C1 + (size_t)r0 * ldc1 + col)       = make_float2(d.x, d.y);
            *(float2*)(C1 + (size_t)(r0 + 8) * ldc1 + col) = make_float2(d.z, d.w);
        }
    }
}

// ---------------------------------------------------------------------------
// Fused C GEMM: ALL modules in one launch. grid = (2, 2040).
// ---------------------------------------------------------------------------
__global__ __launch_bounds__(256, 2)
void gemm_c(const float* __restrict__ fcw)
{
    extern __shared__ float gsm[];
    const int bn = blockIdx.x;
    const int tid = threadIdx.x;
    const int wid = tid >> 5;
    const int lane = tid & 31;
    const int grp = lane >> 2;
    const int tig = lane & 3;
    const int warpRow = wid >> 1;
    const int warpCol = wid & 1;
    const int ldr = tid >> 1;
    const int ldk = (tid & 1) << 2;

    int Y = blockIdx.y;
    int m = 0, base = 0, cnt = 1024;
    while (Y >= base + cnt && m < 7) { base += cnt; m++; cnt >>= 1; }
    const int ty = Y - base;

    const float* Ag = g_ht + xpoff(m) + (size_t)(ty * 128 + ldr) * 128 + ldk;
    const float* Bg = fcw + 128 * m + (size_t)(bn * 128 + ldr) * 1024 + ldk;

    float4 acc[2][8];
#pragma unroll
    for (int i = 0; i < 2; i++)
#pragma unroll
        for (int j = 0; j < 8; j++) acc[i][j] = make_float4(0.f, 0.f, 0.f, 0.f);

    gemm_core(Ag, Bg, 16, gsm, ldr, ldk, warpRow * 32 + grp, warpCol * 64 + grp, tig, acc);

    float* C = g_c + coff(m);
#pragma unroll
    for (int nt = 0; nt < 8; nt++) {
        const int col = bn * 128 + warpCol * 64 + nt * 8 + tig * 2;
#pragma unroll
        for (int mt = 0; mt < 2; mt++) {
            const int r0 = ty * 128 + warpRow * 32 + mt * 16 + grp;
            float4 d = acc[mt][nt];
            *(float2*)(C + (size_t)r0 * 256 + col)       = make_float2(d.x, d.y);
            *(float2*)(C + (size_t)(r0 + 8) * 256 + col) = make_float2(d.z, d.w);
        }
    }
}

// ---------------------------------------------------------------------------
// Chain kernel: 128-dim sequential recurrence, minimum-latency step.
//  - 128 threads, ONE thread per output row; full 128-wide W row pinned in
//    32 float4 registers; full dot computed in-thread (no shuffles).
//  - h reads are uniform-address -> pure LDS broadcast (conflict-free).
//  - double-buffered h, ONE __syncthreads per step.
//  - per-row scalar inputs prefetched distance-2 via __ldg (loop unrolled x2
//    so prefetch slots are compile-time).
//  - fast tanh: 1 - 2/(e^{2x}+1) via __expf (+clamp).
// ---------------------------------------------------------------------------
template<int MM>
__global__ __launch_bounds__(128, 1)
void chain_kernel(const float* __restrict__ Whh, const float* __restrict__ bih,
                  const float* __restrict__ bhh)
{
    constexpr int KS  = 2048 >> MM;
    constexpr int NU  = 7 - MM;
    constexpr int NUX = (NU > 0) ? NU : 1;

    const int b = blockIdx.x;
    const int r = threadIdx.x;   // 0..127 : output row within module

    // pinned full W row (128 floats = 32 float4 registers)
    float4 w[32];
    const float4* wrow = (const float4*)(Whh + (size_t)(128 * MM + r) * 1024 + 128 * MM);
#pragma unroll
    for (int q = 0; q < 32; q++) w[q] = __ldg(wrow + q);

    const float bsr = __ldg(bih + 128 * MM + r) + __ldg(bhh + 128 * MM + r);

    __shared__ __align__(16) float hbuf[2][128];
    hbuf[1][r] = 0.f;            // h^{-1} = 0, read at k=0
    __syncthreads();

    const float* xp = g_xp + xpoff(MM) + (size_t)b * 128 + r;
    float* ht = g_ht + xpoff(MM) + (size_t)b * 128 + r;

    // per-stream U base pointers (j = MM+1+e)
    const float* ub[NUX];
#pragma unroll
    for (int e = 0; e < NU; e++) {
        const int j = MM + 1 + e;
        ub[e] = g_u + uoff(j) + (size_t)b * (128 * j) + 128 * MM + r;
    }

    // distance-2 prefetch slots
    float zx0 = __ldg(xp);
    float zx1 = __ldg(xp + 8192);
    float zu0[NUX], zu1[NUX];
#pragma unroll
    for (int e = 0; e < NU; e++) {
        zu0[e] = 0.f;                     // k=0: unused
        zu1[e] = __ldg(ub[e]);            // k=1: t-1 = 2^MM-1 -> index 0
    }

#define CHAIN_STEP(K, ZX, ZU)                                                   \
    do {                                                                        \
        const int kk = (K);                                                     \
        float z = (ZX) + bsr;                                                   \
        if (kk > 0) {                                                           \
            _Pragma("unroll")                                                   \
            for (int e = 0; e < NU; e++) z += (ZU)[e];                          \
        }                                                                       \
        /* prefetch step kk+2 */                                                \
        if (kk + 2 < KS) {                                                      \
            (ZX) = __ldg(xp + (size_t)(kk + 2) * 8192);                         \
            _Pragma("unroll")                                                   \
            for (int e = 0; e < NU; e++) {                                      \
                const int j = MM + 1 + e;                                       \
                const int ti = (((kk + 2) << MM) - 1) >> j;                     \
                (ZU)[e] = __ldg(ub[e] + (size_t)ti * (size_t)(8192 * j));       \
            }                                                                   \
        }                                                                       \
        /* 128-wide dot: broadcast LDS, 8 accumulators */                       \
        const float4* h4 = (const float4*)hbuf[(kk + 1) & 1];                   \
        float a0 = 0.f, a1 = 0.f, a2 = 0.f, a3 = 0.f;                           \
        float a4 = 0.f, a5 = 0.f, a6 = 0.f, a7 = 0.f;                           \
        _Pragma("unroll")                                                       \
        for (int q = 0; q < 4; q++) {                                           \
            float4 h0 = h4[q * 8 + 0], h1 = h4[q * 8 + 1];                      \
            float4 h2 = h4[q * 8 + 2], h3 = h4[q * 8 + 3];                      \
            float4 h5 = h4[q * 8 + 4], h6 = h4[q * 8 + 5];                      \
            float4 h7 = h4[q * 8 + 6], h8 = h4[q * 8 + 7];                      \
            float4 w0 = w[q * 8 + 0], w1 = w[q * 8 + 1];                        \
            float4 w2 = w[q * 8 + 2], w3 = w[q * 8 + 3];                        \
            float4 w5 = w[q * 8 + 4], w6 = w[q * 8 + 5];                        \
            float4 w7 = w[q * 8 + 6], w8 = w[q * 8 + 7];                        \
            a0 = fmaf(w0.x, h0.x, fmaf(w0.y, h0.y, fmaf(w0.z, h0.z, fmaf(w0.w, h0.w, a0)))); \
            a1 = fmaf(w1.x, h1.x, fmaf(w1.y, h1.y, fmaf(w1.z, h1.z, fmaf(w1.w, h1.w, a1)))); \
            a2 = fmaf(w2.x, h2.x, fmaf(w2.y, h2.y, fmaf(w2.z, h2.z, fmaf(w2.w, h2.w, a2)))); \
            a3 = fmaf(w3.x, h3.x, fmaf(w3.y, h3.y, fmaf(w3.z, h3.z, fmaf(w3.w, h3.w, a3)))); \
            a4 = fmaf(w5.x, h5.x, fmaf(w5.y, h5.y, fmaf(w5.z, h5.z, fmaf(w5.w, h5.w, a4)))); \
            a5 = fmaf(w6.x, h6.x, fmaf(w6.y, h6.y, fmaf(w6.z, h6.z, fmaf(w6.w, h6.w, a5)))); \
            a6 = fmaf(w7.x, h7.x, fmaf(w7.y, h7.y, fmaf(w7.z, h7.z, fmaf(w7.w, h7.w, a6)))); \
            a7 = fmaf(w8.x, h8.x, fmaf(w8.y, h8.y, fmaf(w8.z, h8.z, fmaf(w8.w, h8.w, a7)))); \
        }                                                                       \
        float dot = ((a0 + a1) + (a2 + a3)) + ((a4 + a5) + (a6 + a7));          \
        float xz = fminf(fmaxf(z + dot, -15.f), 15.f);                          \
        float ex = __expf(2.f * xz);                                            \
        float hn = 1.f - __fdividef(2.f, ex + 1.f);                             \
        hbuf[kk & 1][r] = hn;                                                   \
        ht[(size_t)kk * 8192] = hn;                                             \
        __syncthreads();                                                        \
    } while (0)

#pragma unroll 1
    for (int k = 0; k < KS; k += 2) {
        CHAIN_STEP(k,     zx0, zu0);
        CHAIN_STEP(k + 1, zx1, zu1);
    }
#undef CHAIN_STEP
}

// ---------------------------------------------------------------------------
// Gather: y[b][t][i] = fc_b[i] + sum_m C_m[(t>>m)*64 + b][i]
// ---------------------------------------------------------------------------
__global__ __launch_bounds__(256)
void gather_y(const float* __restrict__ fcb, float* __restrict__ out)
{
    const int i = threadIdx.x;
    const float bias = __ldg(fcb + i);
#pragma unroll 1
    for (int e = 0; e < 8; e++) {
        const int tb = blockIdx.x * 8 + e;
        const int t = tb >> 6;
        const int b = tb & 63;
        float v = bias;
#pragma unroll
        for (int m = 0; m < 8; m++)
            v += g_c[coff(m) + (((size_t)((t >> m) * 64 + b)) << 8) + i];
        out[((size_t)b * 2048 + t) * 256 + i] = v;
    }
}

// ---------------------------------------------------------------------------
// Launch: XP(1) -> [chain_j -> U_j]_{j=7..1} -> chain_0 -> C(all, 1) -> gather.
// 18 launches, one stream, graph-capturable, allocation-free.
// ---------------------------------------------------------------------------
extern "C" void kernel_launch(void* const* d_in, const int* in_sizes, int n_in,
                              void* d_out, int out_size)
{
    const float* x   = (const float*)d_in[0];
    const float* wih = (const float*)d_in[1];
    const float* whh = (const float*)d_in[2];
    const float* bih = (const float*)d_in[3];
    const float* bhh = (const float*)d_in[4];
    const float* fcw = (const float*)d_in[5];
    const float* fcb = (const float*)d_in[6];
    float* out = (float*)d_out;

    void* p;
    cudaGetSymbolAddress(&p, g_ht); float* pht = (float*)p;
    cudaGetSymbolAddress(&p, g_u);  float* pu  = (float*)p;

    cudaFuncSetAttribute(gemm_xp, cudaFuncAttributeMaxDynamicSharedMemorySize, GEMM_SMEM_BYTES);
    cudaFuncSetAttribute(gemm_u,  cudaFuncAttributeMaxDynamicSharedMemorySize, GEMM_SMEM_BYTES);
    cudaFuncSetAttribute(gemm_c,  cudaFuncAttributeMaxDynamicSharedMemorySize, GEMM_SMEM_BYTES);

    // all input projections in one full-chip launch (2040 tiles)
    gemm_xp<<<2040, 256, GEMM_SMEM_BYTES>>>(x, wih);

    // cascade: chain_j then U_j (critical path only; C deferred)
#define RUN_STAGE(j)                                                            \
    do {                                                                        \
        chain_kernel<j><<<BATCH, 128>>>(whh, bih, bhh);                         \
        dim3 g((unsigned)(j), (unsigned)(1024 >> (j)));                         \
        gemm_u<<<g, 256, GEMM_SMEM_BYTES>>>(                                    \
            pht + xpoff(j), whh + 128 * (j), pu + uoff(j), 128 * (j));          \
    } while (0)

    RUN_STAGE(7);
    RUN_STAGE(6);
    RUN_STAGE(5);
    RUN_STAGE(4);
    RUN_STAGE(3);
    RUN_STAGE(2);
    RUN_STAGE(1);

    chain_kernel<0><<<BATCH, 128>>>(whh, bih, bhh);

    // all fc contributions in one full-chip launch (2 x 2040 tiles)
    {
        dim3 g(2, 2040);
        gemm_c<<<g, 256, GEMM_SMEM_BYTES>>>(fcw);
    }

    gather_y<<<16384, 256>>>(fcb, out);
#undef RUN_STAGE
}

// round 12
// speedup vs baseline: 1.4429x; 1.1775x over previous
#include <cuda_runtime.h>
#include <math.h>
#include <stdint.h>

#define BATCH 64
#define SEQT  2048
#define ISZ   256
#define HSZ   1024

// ---------------------------------------------------------------------------
// Global scratch (module-compact layouts).
//  XP_m[k][b][128] : input projection at module-m active times (t = k<<m)
//  HT_m[k][b][128] : module-m hidden trajectory samples
//  U_j [k][b][128j]: Whh[0:128j, j-block] @ h_j^(k)
//  C_m [k][b][256] : fc_w[:, m-block] @ h_m^(k)
// ---------------------------------------------------------------------------
#define XP_TOT 33423360ull
#define U_TOT  32374784ull
#define C_TOT  66846720ull
static __device__ float g_xp[XP_TOT];
static __device__ float g_ht[XP_TOT];
static __device__ float g_u [U_TOT];
static __device__ float g_c [C_TOT];

__host__ __device__ constexpr size_t xpoff(int m) {
    return 8192ull * (size_t)(4096 - (4096 >> m));
}
__host__ __device__ constexpr size_t uoff(int j) {
    size_t s = 0;
    for (int p = 1; p < j; p++) s += (size_t)(2048 >> p) * 8192ull * (size_t)p;
    return s;
}
__host__ __device__ constexpr size_t coff(int m) {
    return 16384ull * (size_t)(4096 - (4096 >> m));
}

// ---------------------------------------------------------------------------
// TF32 3-split GEMM core (fp32-accurate): 128x128 CTA tile, 256 thr, 8 warps,
// warp tile 32x64, mma.m16n8k8, double-buffered smem stage.
// ---------------------------------------------------------------------------
__device__ __forceinline__ uint32_t f32_to_tf32(float x) {
    uint32_t r;
    asm("cvt.rna.tf32.f32 %0, %1;" : "=r"(r) : "f"(x));
    return r;
}
__device__ __forceinline__ void mma_tf32(float4& d, const uint32_t a[4],
                                         const uint32_t b0, const uint32_t b1) {
    asm volatile(
        "mma.sync.aligned.m16n8k8.row.col.f32.tf32.tf32.f32 "
        "{%0,%1,%2,%3}, {%4,%5,%6,%7}, {%8,%9}, {%0,%1,%2,%3};"
        : "+f"(d.x), "+f"(d.y), "+f"(d.z), "+f"(d.w)
        : "r"(a[0]), "r"(a[1]), "r"(a[2]), "r"(a[3]), "r"(b0), "r"(b1));
}

#define GST 4224
#define GEMM_SMEM_BYTES (2 * GST * 4)

__device__ __forceinline__ void stage_chunk(float* s, const float4 av, const float4 bv,
                                            int ldr, int ldk)
{
    const float a4[4] = {av.x, av.y, av.z, av.w};
    const float b4[4] = {bv.x, bv.y, bv.z, bv.w};
#pragma unroll
    for (int e = 0; e < 4; e++) {
        uint32_t hi = f32_to_tf32(a4[e]);
        float lo = a4[e] - __uint_as_float(hi);
        s[(ldk + e) * 132 + ldr]        = __uint_as_float(hi);
        s[1056 + (ldk + e) * 132 + ldr] = __uint_as_float(f32_to_tf32(lo));
        uint32_t bhi = f32_to_tf32(b4[e]);
        float blo = b4[e] - __uint_as_float(bhi);
        s[2112 + (ldk + e) * 132 + ldr] = __uint_as_float(bhi);
        s[3168 + (ldk + e) * 132 + ldr] = __uint_as_float(f32_to_tf32(blo));
    }
}

__device__ __forceinline__ void gemm_core(const float* Ag, const float* Bg,
                                          int kchunks, float* gsm,
                                          int ldr, int ldk, int m0, int n0, int tig,
                                          float4 acc[2][8])
{
    stage_chunk(gsm, *(const float4*)Ag, *(const float4*)Bg, ldr, ldk);
    __syncthreads();

    for (int kc = 0; kc < kchunks; kc++) {
        float4 av, bv;
        if (kc + 1 < kchunks) {
            av = *(const float4*)(Ag + (kc + 1) * 8);
            bv = *(const float4*)(Bg + (kc + 1) * 8);
        }
        const float* As_h = gsm + (kc & 1) * GST;
        const float* As_l = As_h + 1056;
        const float* Bs_h = As_h + 2112;
        const float* Bs_l = As_h + 3168;

        uint32_t ah[2][4], al[2][4];
#pragma unroll
        for (int mt = 0; mt < 2; mt++) {
            const int r = m0 + mt * 16;
            ah[mt][0] = __float_as_uint(As_h[tig * 132 + r]);
            ah[mt][1] = __float_as_uint(As_h[tig * 132 + r + 8]);
            ah[mt][2] = __float_as_uint(As_h[(tig + 4) * 132 + r]);
            ah[mt][3] = __float_as_uint(As_h[(tig + 4) * 132 + r + 8]);
            al[mt][0] = __float_as_uint(As_l[tig * 132 + r]);
            al[mt][1] = __float_as_uint(As_l[tig * 132 + r + 8]);
            al[mt][2] = __float_as_uint(As_l[(tig + 4) * 132 + r]);
            al[mt][3] = __float_as_uint(As_l[(tig + 4) * 132 + r + 8]);
        }
#pragma unroll
        for (int nt = 0; nt < 8; nt++) {
            const int cn = n0 + nt * 8;
            uint32_t bh0 = __float_as_uint(Bs_h[tig * 132 + cn]);
            uint32_t bh1 = __float_as_uint(Bs_h[(tig + 4) * 132 + cn]);
            uint32_t bl0 = __float_as_uint(Bs_l[tig * 132 + cn]);
            uint32_t bl1 = __float_as_uint(Bs_l[(tig + 4) * 132 + cn]);
#pragma unroll
            for (int mt = 0; mt < 2; mt++) {
                mma_tf32(acc[mt][nt], al[mt], bh0, bh1);
                mma_tf32(acc[mt][nt], ah[mt], bl0, bl1);
                mma_tf32(acc[mt][nt], ah[mt], bh0, bh1);
            }
        }

        if (kc + 1 < kchunks)
            stage_chunk(gsm + ((kc + 1) & 1) * GST, av, bv, ldr, ldk);
        __syncthreads();
    }
}

// ---------------------------------------------------------------------------
// Fused XP GEMM: one launch for all 8 modules (2040 tiles).
// ---------------------------------------------------------------------------
__global__ __launch_bounds__(256, 2)
void gemm_xp(const float* __restrict__ X, const float* __restrict__ Wih)
{
    extern __shared__ float gsm[];
    const int tid = threadIdx.x;
    const int wid = tid >> 5;
    const int lane = tid & 31;
    const int grp = lane >> 2;
    const int tig = lane & 3;
    const int warpRow = wid >> 1;
    const int warpCol = wid & 1;
    const int ldr = tid >> 1;
    const int ldk = (tid & 1) << 2;

    int Y = blockIdx.x;
    int m = 0, base = 0, cnt = 1024;
    while (Y >= base + cnt && m < 7) { base += cnt; m++; cnt >>= 1; }
    const int ty = Y - base;

    const int rowg = ty * 128 + ldr;
    const int bb = rowg & 63;
    const int kk = rowg >> 6;
    const float* Ag = X + ((size_t)bb * 2048 + ((size_t)kk << m)) * 256 + ldk;
    const float* Bg = Wih + ((size_t)(128 * m + ldr)) * 256 + ldk;

    float4 acc[2][8];
#pragma unroll
    for (int i = 0; i < 2; i++)
#pragma unroll
        for (int j = 0; j < 8; j++) acc[i][j] = make_float4(0.f, 0.f, 0.f, 0.f);

    gemm_core(Ag, Bg, 32, gsm, ldr, ldk, warpRow * 32 + grp, warpCol * 64 + grp, tig, acc);

    float* C = g_xp + xpoff(m);
#pragma unroll
    for (int nt = 0; nt < 8; nt++) {
        const int col = warpCol * 64 + nt * 8 + tig * 2;
#pragma unroll
        for (int mt = 0; mt < 2; mt++) {
            const int r0 = ty * 128 + warpRow * 32 + mt * 16 + grp;
            float4 d = acc[mt][nt];
            *(float2*)(C + (size_t)r0 * 128 + col)       = make_float2(d.x, d.y);
            *(float2*)(C + (size_t)(r0 + 8) * 128 + col) = make_float2(d.z, d.w);
        }
    }
}

// ---------------------------------------------------------------------------
// U-only GEMM for module j: U_j = ht_j @ Whh[0:128j, j-block]^T
// grid = (j, 1024>>j). K = 128.
// ---------------------------------------------------------------------------
__global__ __launch_bounds__(256, 2)
void gemm_u(const float* __restrict__ A, const float* __restrict__ B1,
            float* __restrict__ C1, int ldc1)
{
    extern __shared__ float gsm[];
    const int bn = blockIdx.x;
    const int bm = blockIdx.y;
    const int tid = threadIdx.x;
    const int wid = tid >> 5;
    const int lane = tid & 31;
    const int grp = lane >> 2;
    const int tig = lane & 3;
    const int warpRow = wid >> 1;
    const int warpCol = wid & 1;
    const int ldr = tid >> 1;
    const int ldk = (tid & 1) << 2;

    const float* Ag = A + (size_t)(bm * 128 + ldr) * 128 + ldk;
    const float* Bg = B1 + (size_t)(bn * 128 + ldr) * 1024 + ldk;

    float4 acc[2][8];
#pragma unroll
    for (int i = 0; i < 2; i++)
#pragma unroll
        for (int j = 0; j < 8; j++) acc[i][j] = make_float4(0.f, 0.f, 0.f, 0.f);

    gemm_core(Ag, Bg, 16, gsm, ldr, ldk, warpRow * 32 + grp, warpCol * 64 + grp, tig, acc);

#pragma unroll
    for (int nt = 0; nt < 8; nt++) {
        const int col = bn * 128 + warpCol * 64 + nt * 8 + tig * 2;
#pragma unroll
        for (int mt = 0; mt < 2; mt++) {
            const int r0 = bm * 128 + warpRow * 32 + mt * 16 + grp;
            float4 d = acc[mt][nt];
            *(float2*)(C1 + (size_t)r0 * ldc1 + col)       = make_float2(d.x, d.y);
            *(float2*)(C1 + (size_t)(r0 + 8) * ldc1 + col) = make_float2(d.z, d.w);
        }
    }
}

// ---------------------------------------------------------------------------
// Fused C GEMM: ALL modules in one launch. grid = (2, 2040).
// ---------------------------------------------------------------------------
__global__ __launch_bounds__(256, 2)
void gemm_c(const float* __restrict__ fcw)
{
    extern __shared__ float gsm[];
    const int bn = blockIdx.x;
    const int tid = threadIdx.x;
    const int wid = tid >> 5;
    const int lane = tid & 31;
    const int grp = lane >> 2;
    const int tig = lane & 3;
    const int warpRow = wid >> 1;
    const int warpCol = wid & 1;
    const int ldr = tid >> 1;
    const int ldk = (tid & 1) << 2;

    int Y = blockIdx.y;
    int m = 0, base = 0, cnt = 1024;
    while (Y >= base + cnt && m < 7) { base += cnt; m++; cnt >>= 1; }
    const int ty = Y - base;

    const float* Ag = g_ht + xpoff(m) + (size_t)(ty * 128 + ldr) * 128 + ldk;
    const float* Bg = fcw + 128 * m + (size_t)(bn * 128 + ldr) * 1024 + ldk;

    float4 acc[2][8];
#pragma unroll
    for (int i = 0; i < 2; i++)
#pragma unroll
        for (int j = 0; j < 8; j++) acc[i][j] = make_float4(0.f, 0.f, 0.f, 0.f);

    gemm_core(Ag, Bg, 16, gsm, ldr, ldk, warpRow * 32 + grp, warpCol * 64 + grp, tig, acc);

    float* C = g_c + coff(m);
#pragma unroll
    for (int nt = 0; nt < 8; nt++) {
        const int col = bn * 128 + warpCol * 64 + nt * 8 + tig * 2;
#pragma unroll
        for (int mt = 0; mt < 2; mt++) {
            const int r0 = ty * 128 + warpRow * 32 + mt * 16 + grp;
            float4 d = acc[mt][nt];
            *(float2*)(C + (size_t)r0 * 256 + col)       = make_float2(d.x, d.y);
            *(float2*)(C + (size_t)(r0 + 8) * 256 + col) = make_float2(d.z, d.w);
        }
    }
}

// ---------------------------------------------------------------------------
// Packed f32x2 helpers (FFMA2 — only reachable via PTX fma.rn.f32x2)
// ---------------------------------------------------------------------------
__device__ __forceinline__ unsigned long long fma2_(unsigned long long a,
                                                    unsigned long long b,
                                                    unsigned long long c) {
    unsigned long long d;
    asm("fma.rn.f32x2 %0, %1, %2, %3;" : "=l"(d) : "l"(a), "l"(b), "l"(c));
    return d;
}
__device__ __forceinline__ unsigned long long add2_(unsigned long long a,
                                                    unsigned long long b) {
    unsigned long long d;
    asm("add.rn.f32x2 %0, %1, %2;" : "=l"(d) : "l"(a), "l"(b));
    return d;
}

// ---------------------------------------------------------------------------
// Chain kernel: 128-dim sequential recurrence, minimum-latency step.
//  - 128 threads, ONE thread per output row; W row pinned as 64 packed-f32x2
//    registers; dot = 64 fma.rn.f32x2 (half the FFMA issue) + packed reduce.
//  - h reads: uniform-address LDS.128 broadcast (conflict-free).
//  - double-buffered h, ONE __syncthreads per step.
//  - distance-4 register prefetch of xp/u scalars (loop unrolled x4).
//  - fast tanh: 1 - 2/(e^{2x}+1) via __expf (+clamp).
// ---------------------------------------------------------------------------
template<int MM>
__global__ __launch_bounds__(128, 1)
void chain_kernel(const float* __restrict__ Whh, const float* __restrict__ bih,
                  const float* __restrict__ bhh)
{
    constexpr int KS  = 2048 >> MM;
    constexpr int NU  = 7 - MM;
    constexpr int NUX = (NU > 0) ? NU : 1;

    const int b = blockIdx.x;
    const int r = threadIdx.x;   // 0..127 : output row within module

    // pinned full W row as 64 packed u64 (128 floats)
    unsigned long long w[64];
    {
        const float4* wrow = (const float4*)(Whh + (size_t)(128 * MM + r) * 1024 + 128 * MM);
#pragma unroll
        for (int q = 0; q < 32; q++) {
            float4 v = __ldg(wrow + q);
            union { float2 f; unsigned long long u; } c0, c1;
            c0.f = make_float2(v.x, v.y);
            c1.f = make_float2(v.z, v.w);
            w[2 * q]     = c0.u;
            w[2 * q + 1] = c1.u;
        }
    }

    const float bsr = __ldg(bih + 128 * MM + r) + __ldg(bhh + 128 * MM + r);

    __shared__ __align__(16) float hbuf[2][128];
    hbuf[1][r] = 0.f;            // h^{-1} = 0, read at k=0
    __syncthreads();

    const float* xp = g_xp + xpoff(MM) + (size_t)b * 128 + r;
    float* ht = g_ht + xpoff(MM) + (size_t)b * 128 + r;

    const float* ub[NUX];
#pragma unroll
    for (int e = 0; e < NU; e++) {
        const int j = MM + 1 + e;
        ub[e] = g_u + uoff(j) + (size_t)b * (128 * j) + 128 * MM + r;
    }

    // distance-4 prefetch slots (KS is always a multiple of 4)
    float zx[4];
    float zu[4][NUX];
    zx[0] = __ldg(xp);
#pragma unroll
    for (int e = 0; e < NU; e++) zu[0][e] = 0.f;   // k=0: unused
#pragma unroll
    for (int s = 1; s < 4; s++) {
        zx[s] = __ldg(xp + (size_t)s * 8192);
#pragma unroll
        for (int e = 0; e < NU; e++) {
            const int j = MM + 1 + e;
            const int ti = (((s) << MM) - 1) >> j;
            zu[s][e] = __ldg(ub[e] + (size_t)ti * (size_t)(8192 * j));
        }
    }

#define CHAIN_STEP(K, S)                                                        \
    do {                                                                        \
        const int kk = (K);                                                     \
        float z = zx[S] + bsr;                                                  \
        if (kk > 0) {                                                           \
            _Pragma("unroll")                                                   \
            for (int e = 0; e < NU; e++) z += zu[S][e];                         \
        }                                                                       \
        /* prefetch step kk+4 into slot S */                                    \
        if (kk + 4 < KS) {                                                      \
            zx[S] = __ldg(xp + (size_t)(kk + 4) * 8192);                        \
            _Pragma("unroll")                                                   \
            for (int e = 0; e < NU; e++) {                                      \
                const int j = MM + 1 + e;                                       \
                const int ti = (((kk + 4) << MM) - 1) >> j;                     \
                zu[S][e] = __ldg(ub[e] + (size_t)ti * (size_t)(8192 * j));      \
            }                                                                   \
        }                                                                       \
        /* 128-wide packed dot: broadcast LDS.128, 8 packed accumulators */     \
        const ulonglong2* h8 = (const ulonglong2*)hbuf[(kk + 1) & 1];           \
        unsigned long long p0 = 0, p1 = 0, p2 = 0, p3 = 0;                      \
        unsigned long long p4 = 0, p5 = 0, p6 = 0, p7 = 0;                      \
        _Pragma("unroll")                                                       \
        for (int q = 0; q < 8; q++) {                                           \
            ulonglong2 hA = h8[q * 4 + 0];                                      \
            ulonglong2 hB = h8[q * 4 + 1];                                      \
            ulonglong2 hC = h8[q * 4 + 2];                                      \
            ulonglong2 hD = h8[q * 4 + 3];                                      \
            p0 = fma2_(w[q * 8 + 0], hA.x, p0);                                 \
            p1 = fma2_(w[q * 8 + 1], hA.y, p1);                                 \
            p2 = fma2_(w[q * 8 + 2], hB.x, p2);                                 \
            p3 = fma2_(w[q * 8 + 3], hB.y, p3);                                 \
            p4 = fma2_(w[q * 8 + 4], hC.x, p4);                                 \
            p5 = fma2_(w[q * 8 + 5], hC.y, p5);                                 \
            p6 = fma2_(w[q * 8 + 6], hD.x, p6);                                 \
            p7 = fma2_(w[q * 8 + 7], hD.y, p7);                                 \
        }                                                                       \
        unsigned long long s01 = add2_(p0, p1), s23 = add2_(p2, p3);            \
        unsigned long long s45 = add2_(p4, p5), s67 = add2_(p6, p7);            \
        unsigned long long sAll = add2_(add2_(s01, s23), add2_(s45, s67));      \
        union { float2 f; unsigned long long u; } fin;                          \
        fin.u = sAll;                                                           \
        float dot = fin.f.x + fin.f.y;                                          \
        float xz = fminf(fmaxf(z + dot, -15.f), 15.f);                          \
        float ex = __expf(2.f * xz);                                            \
        float hn = 1.f - __fdividef(2.f, ex + 1.f);                             \
        hbuf[kk & 1][r] = hn;                                                   \
        ht[(size_t)kk * 8192] = hn;                                             \
        __syncthreads();                                                        \
    } while (0)

#pragma unroll 1
    for (int k = 0; k < KS; k += 4) {
        CHAIN_STEP(k,     0);
        CHAIN_STEP(k + 1, 1);
        CHAIN_STEP(k + 2, 2);
        CHAIN_STEP(k + 3, 3);
    }
#undef CHAIN_STEP
}

// ---------------------------------------------------------------------------
// Gather: y[b][t][i] = fc_b[i] + sum_m C_m[(t>>m)*64 + b][i]
// ---------------------------------------------------------------------------
__global__ __launch_bounds__(256)
void gather_y(const float* __restrict__ fcb, float* __restrict__ out)
{
    const int i = threadIdx.x;
    const float bias = __ldg(fcb + i);
#pragma unroll 1
    for (int e = 0; e < 8; e++) {
        const int tb = blockIdx.x * 8 + e;
        const int t = tb >> 6;
        const int b = tb & 63;
        float v = bias;
#pragma unroll
        for (int m = 0; m < 8; m++)
            v += g_c[coff(m) + (((size_t)((t >> m) * 64 + b)) << 8) + i];
        out[((size_t)b * 2048 + t) * 256 + i] = v;
    }
}

// ---------------------------------------------------------------------------
// Launch: XP(1) -> [chain_j -> U_j]_{j=7..1} -> chain_0 -> C(all, 1) -> gather.
// 18 launches, one stream, graph-capturable, allocation-free.
// ---------------------------------------------------------------------------
extern "C" void kernel_launch(void* const* d_in, const int* in_sizes, int n_in,
                              void* d_out, int out_size)
{
    const float* x   = (const float*)d_in[0];
    const float* wih = (const float*)d_in[1];
    const float* whh = (const float*)d_in[2];
    const float* bih = (const float*)d_in[3];
    const float* bhh = (const float*)d_in[4];
    const float* fcw = (const float*)d_in[5];
    const float* fcb = (const float*)d_in[6];
    float* out = (float*)d_out;

    void* p;
    cudaGetSymbolAddress(&p, g_ht); float* pht = (float*)p;
    cudaGetSymbolAddress(&p, g_u);  float* pu  = (float*)p;

    cudaFuncSetAttribute(gemm_xp, cudaFuncAttributeMaxDynamicSharedMemorySize, GEMM_SMEM_BYTES);
    cudaFuncSetAttribute(gemm_u,  cudaFuncAttributeMaxDynamicSharedMemorySize, GEMM_SMEM_BYTES);
    cudaFuncSetAttribute(gemm_c,  cudaFuncAttributeMaxDynamicSharedMemorySize, GEMM_SMEM_BYTES);

    // all input projections in one full-chip launch (2040 tiles)
    gemm_xp<<<2040, 256, GEMM_SMEM_BYTES>>>(x, wih);

    // cascade: chain_j then U_j (critical path only; C deferred)
#define RUN_STAGE(j)                                                            \
    do {                                                                        \
        chain_kernel<j><<<BATCH, 128>>>(whh, bih, bhh);                         \
        dim3 g((unsigned)(j), (unsigned)(1024 >> (j)));                         \
        gemm_u<<<g, 256, GEMM_SMEM_BYTES>>>(                                    \
            pht + xpoff(j), whh + 128 * (j), pu + uoff(j), 128 * (j));          \
    } while (0)

    RUN_STAGE(7);
    RUN_STAGE(6);
    RUN_STAGE(5);
    RUN_STAGE(4);
    RUN_STAGE(3);
    RUN_STAGE(2);
    RUN_STAGE(1);

    chain_kernel<0><<<BATCH, 128>>>(whh, bih, bhh);

    // all fc contributions in one full-chip launch (2 x 2040 tiles)
    {
        dim3 g(2, 2040);
        gemm_c<<<g, 256, GEMM_SMEM_BYTES>>>(fcw);
    }

    gather_y<<<16384, 256>>>(fcb, out);
#undef RUN_STAGE
}

// round 14
// speedup vs baseline: 1.4433x; 1.0003x over previous
#include <cuda_runtime.h>
#include <math.h>
#include <stdint.h>

#define BATCH 64
#define SEQT  2048
#define ISZ   256
#define HSZ   1024

// ---------------------------------------------------------------------------
// Global scratch (module-compact layouts).
//  XP_m[k][b][128] : input projection at module-m active times (t = k<<m)
//  HT_m[k][b][128] : module-m hidden trajectory samples
//  U_j [k][b][128j]: Whh[0:128j, j-block] @ h_j^(k)
//  C_m [k][b][256] : fc_w[:, m-block] @ h_m^(k)
// ---------------------------------------------------------------------------
#define XP_TOT 33423360ull
#define U_TOT  32374784ull
#define C_TOT  66846720ull
static __device__ float g_xp[XP_TOT];
static __device__ float g_ht[XP_TOT];
static __device__ float g_u [U_TOT];
static __device__ float g_c [C_TOT];

__host__ __device__ constexpr size_t xpoff(int m) {
    return 8192ull * (size_t)(4096 - (4096 >> m));
}
__host__ __device__ constexpr size_t uoff(int j) {
    size_t s = 0;
    for (int p = 1; p < j; p++) s += (size_t)(2048 >> p) * 8192ull * (size_t)p;
    return s;
}
__host__ __device__ constexpr size_t coff(int m) {
    return 16384ull * (size_t)(4096 - (4096 >> m));
}

// ---------------------------------------------------------------------------
// TF32 3-split GEMM core (fp32-accurate): 128x128 CTA tile, 256 thr, 8 warps,
// warp tile 32x64, mma.m16n8k8, double-buffered smem stage.
// ---------------------------------------------------------------------------
__device__ __forceinline__ uint32_t f32_to_tf32(float x) {
    uint32_t r;
    asm("cvt.rna.tf32.f32 %0, %1;" : "=r"(r) : "f"(x));
    return r;
}
__device__ __forceinline__ void mma_tf32(float4& d, const uint32_t a[4],
                                         const uint32_t b0, const uint32_t b1) {
    asm volatile(
        "mma.sync.aligned.m16n8k8.row.col.f32.tf32.tf32.f32 "
        "{%0,%1,%2,%3}, {%4,%5,%6,%7}, {%8,%9}, {%0,%1,%2,%3};"
        : "+f"(d.x), "+f"(d.y), "+f"(d.z), "+f"(d.w)
        : "r"(a[0]), "r"(a[1]), "r"(a[2]), "r"(a[3]), "r"(b0), "r"(b1));
}

#define GST 4224
#define GEMM_SMEM_BYTES (2 * GST * 4)

__device__ __forceinline__ void stage_chunk(float* s, const float4 av, const float4 bv,
                                            int ldr, int ldk)
{
    const float a4[4] = {av.x, av.y, av.z, av.w};
    const float b4[4] = {bv.x, bv.y, bv.z, bv.w};
#pragma unroll
    for (int e = 0; e < 4; e++) {
        uint32_t hi = f32_to_tf32(a4[e]);
        float lo = a4[e] - __uint_as_float(hi);
        s[(ldk + e) * 132 + ldr]        = __uint_as_float(hi);
        s[1056 + (ldk + e) * 132 + ldr] = __uint_as_float(f32_to_tf32(lo));
        uint32_t bhi = f32_to_tf32(b4[e]);
        float blo = b4[e] - __uint_as_float(bhi);
        s[2112 + (ldk + e) * 132 + ldr] = __uint_as_float(bhi);
        s[3168 + (ldk + e) * 132 + ldr] = __uint_as_float(f32_to_tf32(blo));
    }
}

__device__ __forceinline__ void gemm_core(const float* Ag, const float* Bg,
                                          int kchunks, float* gsm,
                                          int ldr, int ldk, int m0, int n0, int tig,
                                          float4 acc[2][8])
{
    stage_chunk(gsm, *(const float4*)Ag, *(const float4*)Bg, ldr, ldk);
    __syncthreads();

    for (int kc = 0; kc < kchunks; kc++) {
        float4 av, bv;
        if (kc + 1 < kchunks) {
            av = *(const float4*)(Ag + (kc + 1) * 8);
            bv = *(const float4*)(Bg + (kc + 1) * 8);
        }
        const float* As_h = gsm + (kc & 1) * GST;
        const float* As_l = As_h + 1056;
        const float* Bs_h = As_h + 2112;
        const float* Bs_l = As_h + 3168;

        uint32_t ah[2][4], al[2][4];
#pragma unroll
        for (int mt = 0; mt < 2; mt++) {
            const int r = m0 + mt * 16;
            ah[mt][0] = __float_as_uint(As_h[tig * 132 + r]);
            ah[mt][1] = __float_as_uint(As_h[tig * 132 + r + 8]);
            ah[mt][2] = __float_as_uint(As_h[(tig + 4) * 132 + r]);
            ah[mt][3] = __float_as_uint(As_h[(tig + 4) * 132 + r + 8]);
            al[mt][0] = __float_as_uint(As_l[tig * 132 + r]);
            al[mt][1] = __float_as_uint(As_l[tig * 132 + r + 8]);
            al[mt][2] = __float_as_uint(As_l[(tig + 4) * 132 + r]);
            al[mt][3] = __float_as_uint(As_l[(tig + 4) * 132 + r + 8]);
        }
#pragma unroll
        for (int nt = 0; nt < 8; nt++) {
            const int cn = n0 + nt * 8;
            uint32_t bh0 = __float_as_uint(Bs_h[tig * 132 + cn]);
            uint32_t bh1 = __float_as_uint(Bs_h[(tig + 4) * 132 + cn]);
            uint32_t bl0 = __float_as_uint(Bs_l[tig * 132 + cn]);
            uint32_t bl1 = __float_as_uint(Bs_l[(tig + 4) * 132 + cn]);
#pragma unroll
            for (int mt = 0; mt < 2; mt++) {
                mma_tf32(acc[mt][nt], al[mt], bh0, bh1);
                mma_tf32(acc[mt][nt], ah[mt], bl0, bl1);
                mma_tf32(acc[mt][nt], ah[mt], bh0, bh1);
            }
        }

        if (kc + 1 < kchunks)
            stage_chunk(gsm + ((kc + 1) & 1) * GST, av, bv, ldr, ldk);
        __syncthreads();
    }
}

// ---------------------------------------------------------------------------
// Per-module XP GEMM: XP_m = x(strided t = k<<m) @ Wih[m-block]^T
// grid = (1, 1024>>m), K = 256.
// ---------------------------------------------------------------------------
__global__ __launch_bounds__(256, 2)
void gemm_xp1(const float* __restrict__ X, const float* __restrict__ Wih, int m)
{
    extern __shared__ float gsm[];
    const int tid = threadIdx.x;
    const int wid = tid >> 5;
    const int lane = tid & 31;
    const int grp = lane >> 2;
    const int tig = lane & 3;
    const int warpRow = wid >> 1;
    const int warpCol = wid & 1;
    const int ldr = tid >> 1;
    const int ldk = (tid & 1) << 2;
    const int ty = blockIdx.y;

    const int rowg = ty * 128 + ldr;
    const int bb = rowg & 63;
    const int kk = rowg >> 6;
    const float* Ag = X + ((size_t)bb * 2048 + ((size_t)kk << m)) * 256 + ldk;
    const float* Bg = Wih + ((size_t)(128 * m + ldr)) * 256 + ldk;

    float4 acc[2][8];
#pragma unroll
    for (int i = 0; i < 2; i++)
#pragma unroll
        for (int j = 0; j < 8; j++) acc[i][j] = make_float4(0.f, 0.f, 0.f, 0.f);

    gemm_core(Ag, Bg, 32, gsm, ldr, ldk, warpRow * 32 + grp, warpCol * 64 + grp, tig, acc);

    float* C = g_xp + xpoff(m);
#pragma unroll
    for (int nt = 0; nt < 8; nt++) {
        const int col = warpCol * 64 + nt * 8 + tig * 2;
#pragma unroll
        for (int mt = 0; mt < 2; mt++) {
            const int r0 = ty * 128 + warpRow * 32 + mt * 16 + grp;
            float4 d = acc[mt][nt];
            *(float2*)(C + (size_t)r0 * 128 + col)       = make_float2(d.x, d.y);
            *(float2*)(C + (size_t)(r0 + 8) * 128 + col) = make_float2(d.z, d.w);
        }
    }
}

// ---------------------------------------------------------------------------
// U-only GEMM for module j: U_j = ht_j @ Whh[0:128j, j-block]^T
// grid = (j, 1024>>j). K = 128.
// ---------------------------------------------------------------------------
__global__ __launch_bounds__(256, 2)
void gemm_u(const float* __restrict__ A, const float* __restrict__ B1,
            float* __restrict__ C1, int ldc1)
{
    extern __shared__ float gsm[];
    const int bn = blockIdx.x;
    const int bm = blockIdx.y;
    const int tid = threadIdx.x;
    const int wid = tid >> 5;
    const int lane = tid & 31;
    const int grp = lane >> 2;
    const int tig = lane & 3;
    const int warpRow = wid >> 1;
    const int warpCol = wid & 1;
    const int ldr = tid >> 1;
    const int ldk = (tid & 1) << 2;

    const float* Ag = A + (size_t)(bm * 128 + ldr) * 128 + ldk;
    const float* Bg = B1 + (size_t)(bn * 128 + ldr) * 1024 + ldk;

    float4 acc[2][8];
#pragma unroll
    for (int i = 0; i < 2; i++)
#pragma unroll
        for (int j = 0; j < 8; j++) acc[i][j] = make_float4(0.f, 0.f, 0.f, 0.f);

    gemm_core(Ag, Bg, 16, gsm, ldr, ldk, warpRow * 32 + grp, warpCol * 64 + grp, tig, acc);

#pragma unroll
    for (int nt = 0; nt < 8; nt++) {
        const int col = bn * 128 + warpCol * 64 + nt * 8 + tig * 2;
#pragma unroll
        for (int mt = 0; mt < 2; mt++) {
            const int r0 = bm * 128 + warpRow * 32 + mt * 16 + grp;
            float4 d = acc[mt][nt];
            *(float2*)(C1 + (size_t)r0 * ldc1 + col)       = make_float2(d.x, d.y);
            *(float2*)(C1 + (size_t)(r0 + 8) * ldc1 + col) = make_float2(d.z, d.w);
        }
    }
}

// ---------------------------------------------------------------------------
// Per-module C GEMM: C_m = ht_m @ fcw[:, m-block]^T. grid = (2, 1024>>m), K=128.
// ---------------------------------------------------------------------------
__global__ __launch_bounds__(256, 2)
void gemm_c1(const float* __restrict__ fcw, int m)
{
    extern __shared__ float gsm[];
    const int bn = blockIdx.x;
    const int ty = blockIdx.y;
    const int tid = threadIdx.x;
    const int wid = tid >> 5;
    const int lane = tid & 31;
    const int grp = lane >> 2;
    const int tig = lane & 3;
    const int warpRow = wid >> 1;
    const int warpCol = wid & 1;
    const int ldr = tid >> 1;
    const int ldk = (tid & 1) << 2;

    const float* Ag = g_ht + xpoff(m) + (size_t)(ty * 128 + ldr) * 128 + ldk;
    const float* Bg = fcw + 128 * m + (size_t)(bn * 128 + ldr) * 1024 + ldk;

    float4 acc[2][8];
#pragma unroll
    for (int i = 0; i < 2; i++)
#pragma unroll
        for (int j = 0; j < 8; j++) acc[i][j] = make_float4(0.f, 0.f, 0.f, 0.f);

    gemm_core(Ag, Bg, 16, gsm, ldr, ldk, warpRow * 32 + grp, warpCol * 64 + grp, tig, acc);

    float* C = g_c + coff(m);
#pragma unroll
    for (int nt = 0; nt < 8; nt++) {
        const int col = bn * 128 + warpCol * 64 + nt * 8 + tig * 2;
#pragma unroll
        for (int mt = 0; mt < 2; mt++) {
            const int r0 = ty * 128 + warpRow * 32 + mt * 16 + grp;
            float4 d = acc[mt][nt];
            *(float2*)(C + (size_t)r0 * 256 + col)       = make_float2(d.x, d.y);
            *(float2*)(C + (size_t)(r0 + 8) * 256 + col) = make_float2(d.z, d.w);
        }
    }
}

// ---------------------------------------------------------------------------
// Packed f32x2 helpers (FFMA2 — only reachable via PTX fma.rn.f32x2)
// ---------------------------------------------------------------------------
__device__ __forceinline__ unsigned long long fma2_(unsigned long long a,
                                                    unsigned long long b,
                                                    unsigned long long c) {
    unsigned long long d;
    asm("fma.rn.f32x2 %0, %1, %2, %3;" : "=l"(d) : "l"(a), "l"(b), "l"(c));
    return d;
}
__device__ __forceinline__ unsigned long long add2_(unsigned long long a,
                                                    unsigned long long b) {
    unsigned long long d;
    asm("add.rn.f32x2 %0, %1, %2;" : "=l"(d) : "l"(a), "l"(b));
    return d;
}

// ---------------------------------------------------------------------------
// Chain kernel: 128-dim sequential recurrence, minimum-latency step.
// ---------------------------------------------------------------------------
template<int MM>
__global__ __launch_bounds__(128, 1)
void chain_kernel(const float* __restrict__ Whh, const float* __restrict__ bih,
                  const float* __restrict__ bhh)
{
    constexpr int KS  = 2048 >> MM;
    constexpr int NU  = 7 - MM;
    constexpr int NUX = (NU > 0) ? NU : 1;

    const int b = blockIdx.x;
    const int r = threadIdx.x;

    unsigned long long w[64];
    {
        const float4* wrow = (const float4*)(Whh + (size_t)(128 * MM + r) * 1024 + 128 * MM);
#pragma unroll
        for (int q = 0; q < 32; q++) {
            float4 v = __ldg(wrow + q);
            union { float2 f; unsigned long long u; } c0, c1;
            c0.f = make_float2(v.x, v.y);
            c1.f = make_float2(v.z, v.w);
            w[2 * q]     = c0.u;
            w[2 * q + 1] = c1.u;
        }
    }

    const float bsr = __ldg(bih + 128 * MM + r) + __ldg(bhh + 128 * MM + r);

    __shared__ __align__(16) float hbuf[2][128];
    hbuf[1][r] = 0.f;
    __syncthreads();

    const float* xp = g_xp + xpoff(MM) + (size_t)b * 128 + r;
    float* ht = g_ht + xpoff(MM) + (size_t)b * 128 + r;

    const float* ub[NUX];
#pragma unroll
    for (int e = 0; e < NU; e++) {
        const int j = MM + 1 + e;
        ub[e] = g_u + uoff(j) + (size_t)b * (128 * j) + 128 * MM + r;
    }

    float zx[4];
    float zu[4][NUX];
    zx[0] = __ldg(xp);
#pragma unroll
    for (int e = 0; e < NU; e++) zu[0][e] = 0.f;
#pragma unroll
    for (int s = 1; s < 4; s++) {
        zx[s] = __ldg(xp + (size_t)s * 8192);
#pragma unroll
        for (int e = 0; e < NU; e++) {
            const int j = MM + 1 + e;
            const int ti = (((s) << MM) - 1) >> j;
            zu[s][e] = __ldg(ub[e] + (size_t)ti * (size_t)(8192 * j));
        }
    }

#define CHAIN_STEP(K, S)                                                        \
    do {                                                                        \
        const int kk = (K);                                                     \
        float z = zx[S] + bsr;                                                  \
        if (kk > 0) {                                                           \
            _Pragma("unroll")                                                   \
            for (int e = 0; e < NU; e++) z += zu[S][e];                         \
        }                                                                       \
        if (kk + 4 < KS) {                                                      \
            zx[S] = __ldg(xp + (size_t)(kk + 4) * 8192);                        \
            _Pragma("unroll")                                                   \
            for (int e = 0; e < NU; e++) {                                      \
                const int j = MM + 1 + e;                                       \
                const int ti = (((kk + 4) << MM) - 1) >> j;                     \
                zu[S][e] = __ldg(ub[e] + (size_t)ti * (size_t)(8192 * j));      \
            }                                                                   \
        }                                                                       \
        const ulonglong2* h8 = (const ulonglong2*)hbuf[(kk + 1) & 1];           \
        unsigned long long p0 = 0, p1 = 0, p2 = 0, p3 = 0;                      \
        unsigned long long p4 = 0, p5 = 0, p6 = 0, p7 = 0;                      \
        _Pragma("unroll")                                                       \
        for (int q = 0; q < 8; q++) {                                           \
            ulonglong2 hA = h8[q * 4 + 0];                                      \
            ulonglong2 hB = h8[q * 4 + 1];                                      \
            ulonglong2 hC = h8[q * 4 + 2];                                      \
            ulonglong2 hD = h8[q * 4 + 3];                                      \
            p0 = fma2_(w[q * 8 + 0], hA.x, p0);                                 \
            p1 = fma2_(w[q * 8 + 1], hA.y, p1);                                 \
            p2 = fma2_(w[q * 8 + 2], hB.x, p2);                                 \
            p3 = fma2_(w[q * 8 + 3], hB.y, p3);                                 \
            p4 = fma2_(w[q * 8 + 4], hC.x, p4);                                 \
            p5 = fma2_(w[q * 8 + 5], hC.y, p5);                                 \
            p6 = fma2_(w[q * 8 + 6], hD.x, p6);                                 \
            p7 = fma2_(w[q * 8 + 7], hD.y, p7);                                 \
        }                                                                       \
        unsigned long long s01 = add2_(p0, p1), s23 = add2_(p2, p3);            \
        unsigned long long s45 = add2_(p4, p5), s67 = add2_(p6, p7);            \
        unsigned long long sAll = add2_(add2_(s01, s23), add2_(s45, s67));      \
        union { float2 f; unsigned long long u; } fin;                          \
        fin.u = sAll;                                                           \
        float dot = fin.f.x + fin.f.y;                                          \
        float xz = z + dot;                                                     \
        float ex = __expf(2.f * xz);                                            \
        float hn = 1.f - __fdividef(2.f, ex + 1.f);                             \
        hbuf[kk & 1][r] = hn;                                                   \
        ht[(size_t)kk * 8192] = hn;                                             \
        __syncthreads();                                                        \
    } while (0)

#pragma unroll 1
    for (int k = 0; k < KS; k += 4) {
        CHAIN_STEP(k,     0);
        CHAIN_STEP(k + 1, 1);
        CHAIN_STEP(k + 2, 2);
        CHAIN_STEP(k + 3, 3);
    }
#undef CHAIN_STEP
}

// ---------------------------------------------------------------------------
// Gather: y[b][t][i] = fc_b[i] + sum_m C_m[(t>>m)*64 + b][i]
// ---------------------------------------------------------------------------
__global__ __launch_bounds__(256)
void gather_y(const float* __restrict__ fcb, float* __restrict__ out)
{
    const int i = threadIdx.x;
    const float bias = __ldg(fcb + i);
#pragma unroll 1
    for (int e = 0; e < 8; e++) {
        const int tb = blockIdx.x * 8 + e;
        const int t = tb >> 6;
        const int b = tb & 63;
        float v = bias;
#pragma unroll
        for (int m = 0; m < 8; m++)
            v += g_c[coff(m) + (((size_t)((t >> m) * 64 + b)) << 8) + i];
        out[((size_t)b * 2048 + t) * 256 + i] = v;
    }
}

// ---------------------------------------------------------------------------
// Launch DAG with side stream. CAPTURE-SAFE ORDERING: every
// cudaStreamWaitEvent is enqueued AFTER its cudaEventRecord (host order).
//   main(0): XP7 -> [chain_j -> rec(evChain_j) -> U_j -> wait(evXP_{j-1})]_{7..1}
//            -> chain0 -> rec(evChain0) -> wait(evSideEnd) -> gather
//   side(s1): wait(evFork) -> XP6..XP0 (rec evXP_m)
//             interleaved: wait(evChain_j) -> C_j  (enqueued right after each rec)
//             -> C0 -> rec(evSideEnd)
// Serial fallback if stream/event creation failed.
// ---------------------------------------------------------------------------
static cudaStream_t g_s1 = 0;
static cudaEvent_t  g_evFork = 0, g_evSideEnd = 0;
static cudaEvent_t  g_evXP[8] = {0}, g_evChain[8] = {0};
static int g_streams_ok = -1;

static void init_streams_once()
{
    if (g_streams_ok != -1) return;
    g_streams_ok = 1;
    if (cudaStreamCreateWithFlags(&g_s1, cudaStreamNonBlocking) != cudaSuccess) {
        g_streams_ok = 0; return;
    }
    if (cudaEventCreateWithFlags(&g_evFork, cudaEventDisableTiming) != cudaSuccess ||
        cudaEventCreateWithFlags(&g_evSideEnd, cudaEventDisableTiming) != cudaSuccess) {
        g_streams_ok = 0; return;
    }
    for (int m = 0; m < 8; m++) {
        if (cudaEventCreateWithFlags(&g_evXP[m], cudaEventDisableTiming) != cudaSuccess ||
            cudaEventCreateWithFlags(&g_evChain[m], cudaEventDisableTiming) != cudaSuccess) {
            g_streams_ok = 0; return;
        }
    }
}

template<int J>
static void launch_chain(const float* whh, const float* bih, const float* bhh)
{
    chain_kernel<J><<<BATCH, 128>>>(whh, bih, bhh);
}
typedef void (*chain_fn)(const float*, const float*, const float*);
static const chain_fn CHAINS[8] = {
    launch_chain<0>, launch_chain<1>, launch_chain<2>, launch_chain<3>,
    launch_chain<4>, launch_chain<5>, launch_chain<6>, launch_chain<7>
};

extern "C" void kernel_launch(void* const* d_in, const int* in_sizes, int n_in,
                              void* d_out, int out_size)
{
    const float* x   = (const float*)d_in[0];
    const float* wih = (const float*)d_in[1];
    const float* whh = (const float*)d_in[2];
    const float* bih = (const float*)d_in[3];
    const float* bhh = (const float*)d_in[4];
    const float* fcw = (const float*)d_in[5];
    const float* fcb = (const float*)d_in[6];
    float* out = (float*)d_out;

    void* p;
    cudaGetSymbolAddress(&p, g_ht); float* pht = (float*)p;
    cudaGetSymbolAddress(&p, g_u);  float* pu  = (float*)p;

    cudaFuncSetAttribute(gemm_xp1, cudaFuncAttributeMaxDynamicSharedMemorySize, GEMM_SMEM_BYTES);
    cudaFuncSetAttribute(gemm_u,   cudaFuncAttributeMaxDynamicSharedMemorySize, GEMM_SMEM_BYTES);
    cudaFuncSetAttribute(gemm_c1,  cudaFuncAttributeMaxDynamicSharedMemorySize, GEMM_SMEM_BYTES);

    init_streams_once();

    if (g_streams_ok) {
        // fork side stream off the main stream
        cudaEventRecord(g_evFork, 0);
        cudaStreamWaitEvent(g_s1, g_evFork, 0);

        // side: XP for modules 6..0 (records precede the main-stream waits below)
        for (int m = 6; m >= 0; m--) {
            dim3 g(1, (unsigned)(1024 >> m));
            gemm_xp1<<<g, 256, GEMM_SMEM_BYTES, g_s1>>>(x, wih, m);
            cudaEventRecord(g_evXP[m], g_s1);
        }

        // main: XP7 (critical path)
        {
            dim3 g(1, 8);
            gemm_xp1<<<g, 256, GEMM_SMEM_BYTES>>>(x, wih, 7);
        }

        // cascade: record evChain_j BEFORE enqueueing the side-stream wait on it
        for (int j = 7; j >= 1; j--) {
            CHAINS[j](whh, bih, bhh);
            cudaEventRecord(g_evChain[j], 0);

            // side: C_j (off critical path), wait enqueued after the record
            cudaStreamWaitEvent(g_s1, g_evChain[j], 0);
            {
                dim3 gc(2, (unsigned)(1024 >> j));
                gemm_c1<<<gc, 256, GEMM_SMEM_BYTES, g_s1>>>(fcw, j);
            }

            // main: U_j, then gate on XP_{j-1} (recorded earlier)
            dim3 g((unsigned)j, (unsigned)(1024 >> j));
            gemm_u<<<g, 256, GEMM_SMEM_BYTES>>>(
                pht + xpoff(j), whh + 128 * j, pu + uoff(j), 128 * j);
            cudaStreamWaitEvent(0, g_evXP[j - 1], 0);
        }

        CHAINS[0](whh, bih, bhh);
        cudaEventRecord(g_evChain[0], 0);

        cudaStreamWaitEvent(g_s1, g_evChain[0], 0);
        {
            dim3 gc(2, 1024);
            gemm_c1<<<gc, 256, GEMM_SMEM_BYTES, g_s1>>>(fcw, 0);
        }
        cudaEventRecord(g_evSideEnd, g_s1);

        // join side stream back into main before gather
        cudaStreamWaitEvent(0, g_evSideEnd, 0);
        gather_y<<<16384, 256>>>(fcb, out);
    } else {
        // ---- serial fallback (R12-equivalent) ----
        for (int m = 7; m >= 0; m--) {
            dim3 g(1, (unsigned)(1024 >> m));
            gemm_xp1<<<g, 256, GEMM_SMEM_BYTES>>>(x, wih, m);
        }
        for (int j = 7; j >= 1; j--) {
            CHAINS[j](whh, bih, bhh);
            dim3 g((unsigned)j, (unsigned)(1024 >> j));
            gemm_u<<<g, 256, GEMM_SMEM_BYTES>>>(
                pht + xpoff(j), whh + 128 * j, pu + uoff(j), 128 * j);
        }
        CHAINS[0](whh, bih, bhh);
        for (int m = 7; m >= 0; m--) {
            dim3 g(2, (unsigned)(1024 >> m));
            gemm_c1<<<g, 256, GEMM_SMEM_BYTES>>>(fcw, m);
        }
        gather_y<<<16384, 256>>>(fcb, out);
    }
}